// round 13
// baseline (speedup 1.0000x reference)
#include <cuda_runtime.h>

// Fixed problem dims
#define NB 4
#define NQv 512
#define MMv 512
#define DDv 256
#define HHv 256

// Scratch (device globals: no allocations allowed).
// Projection written as TWO k-half partial sums (no atomics/memset needed);
// the score kernel adds them.
__device__ float g_q0[NB * NQv * HHv];
__device__ float g_q1[NB * NQv * HHv];
__device__ float g_kT0[NB * HHv * MMv];   // [b][h][m] f32 partial
__device__ float g_kT1[NB * HHv * MMv];
__device__ float g_sc[NB * NQv * MMv];    // raw scores [b][n][m]

__device__ __forceinline__ float fex2(float x) {
    float y; asm("ex2.approx.f32 %0, %1;" : "=f"(y) : "f"(x)); return y;
}
__device__ __forceinline__ unsigned long long pk2(float a, float b) {
    unsigned long long r; asm("mov.b64 %0, {%1, %2};" : "=l"(r) : "f"(a), "f"(b)); return r;
}
__device__ __forceinline__ void fma2(unsigned long long &d, unsigned long long a, unsigned long long b) {
    asm("fma.rn.f32x2 %0, %1, %2, %0;" : "+l"(d) : "l"(a), "l"(b));
}
__device__ __forceinline__ float2 up2(unsigned long long v) {
    float2 r; asm("mov.b64 {%0, %1}, %2;" : "=f"(r.x), "=f"(r.y) : "l"(v)); return r;
}
__device__ __forceinline__ unsigned packh2(float lo, float hi) {
    unsigned r; asm("cvt.rn.f16x2.f32 %0, %1, %2;" : "=r"(r) : "f"(hi), "f"(lo)); return r;
}
__device__ __forceinline__ unsigned hadd2(unsigned a, unsigned b) {
    unsigned r; asm("add.f16x2 %0, %1, %2;" : "=r"(r) : "r"(a), "r"(b)); return r;
}
__device__ __forceinline__ unsigned htanh2(unsigned a) {
    unsigned r; asm("tanh.approx.f16x2 %0, %1;" : "=r"(r) : "r"(a)); return r;
}
__device__ __forceinline__ unsigned hfma2(unsigned a, unsigned b, unsigned c) {
    unsigned r; asm("fma.rn.f16x2 %0, %1, %2, %3;" : "=r"(r) : "r"(a), "r"(b), "r"(c)); return r;
}
__device__ __forceinline__ void drain2(unsigned p, float &f0, float &f1) {
    unsigned short lo, hi; float a, b;
    asm("mov.b32 {%0, %1}, %2;" : "=h"(lo), "=h"(hi) : "r"(p));
    asm("cvt.f32.f16 %0, %1;" : "=f"(a) : "h"(lo));
    asm("cvt.f32.f16 %0, %1;" : "=f"(b) : "h"(hi));
    f0 += a; f1 += b;
}

// ---------------------------------------------------------------------------
// K-split projection GEMM: 512 blocks = khalf(2) x {q,k}(2) x 128 tiles.
// Each block: 64x64 tile, K-range 128 (8 slabs), 256 threads, 4x4 micro,
// f32x2 FMAs, double-buffered. Writes f32 partials; consumer adds.
// 3.46 blocks/SM (vs 1.73) fixes the measured grid starvation.
// ---------------------------------------------------------------------------
__global__ __launch_bounds__(256) void proj_kernel(const float* __restrict__ query,
                                                   const float* __restrict__ key,
                                                   const float* __restrict__ Wq,
                                                   const float* __restrict__ Wk)
{
    __shared__ __align__(16) float As[16][68];
    __shared__ __align__(16) float Bs[16][64];

    int bid = blockIdx.x;
    int local = bid & 127;
    int is_k = (bid >> 7) & 1;
    int kh = bid >> 8;                // k-half: 0 or 1
    int row0 = (local >> 2) * 64;
    int col0 = (local & 3) * 64;
    const float* A = is_k ? key : query;
    const float* B = is_k ? Wk : Wq;
    int kbase = kh * 128;

    int t = threadIdx.x;
    int tx = t & 15, ty = t >> 4;
    int arow = t >> 2, akq = t & 3;
    int bk = t >> 4, bh = t & 15;

    const float* Aptr = A + (row0 + arow) * DDv + kbase + akq * 4;
    const float* Bptr = B + (kbase + bk) * HHv + col0 + bh * 4;

    unsigned long long acc[4][2];
#pragma unroll
    for (int i = 0; i < 4; i++) { acc[i][0] = 0ull; acc[i][1] = 0ull; }

    float4 a_n = *(const float4*)(Aptr);
    float4 b_n = *(const float4*)(Bptr);

    for (int k0 = 0; k0 < 128; k0 += 16) {
        As[akq * 4 + 0][arow] = a_n.x;
        As[akq * 4 + 1][arow] = a_n.y;
        As[akq * 4 + 2][arow] = a_n.z;
        As[akq * 4 + 3][arow] = a_n.w;
        *(float4*)&Bs[bk][bh * 4] = b_n;
        __syncthreads();

        if (k0 + 16 < 128) {
            a_n = *(const float4*)(Aptr + k0 + 16);
            b_n = *(const float4*)(Bptr + (k0 + 16) * HHv);
        }

#pragma unroll
        for (int k = 0; k < 16; k++) {
            const unsigned long long* br = (const unsigned long long*)&Bs[k][tx * 4];
            unsigned long long b0 = br[0], b1 = br[1];
#pragma unroll
            for (int i = 0; i < 4; i++) {
                float a = As[k][ty * 4 + i];
                unsigned long long aa = pk2(a, a);
                fma2(acc[i][0], aa, b0);
                fma2(acc[i][1], aa, b1);
            }
        }
        __syncthreads();
    }

    float* gq  = kh ? g_q1  : g_q0;
    float* gkt = kh ? g_kT1 : g_kT0;

#pragma unroll
    for (int i = 0; i < 4; i++) {
        int row = row0 + ty * 4 + i;
        int col = col0 + tx * 4;
        float2 c0 = up2(acc[i][0]);
        float2 c1 = up2(acc[i][1]);
        if (!is_k) {
            *(float4*)(gq + row * HHv + col) = make_float4(c0.x, c0.y, c1.x, c1.y);
        } else {
            int bb = row >> 9, m = row & 511;
            float* base = gkt + (bb * HHv) * MMv + m;
            base[(col + 0) * MMv] = c0.x;
            base[(col + 1) * MMv] = c0.y;
            base[(col + 2) * MMv] = c1.x;
            base[(col + 3) * MMv] = c1.y;
        }
    }
}

// ---------------------------------------------------------------------------
// Score kernel (R9 body + partial-sum inputs): tile (8q x 128m), 128 thr,
// grid 1024. Per h: kv = kT0+kT1 (2 coalesced LDG.32 + FADD + F2FP pack,
// all hidden under the 64-cycle MUFU budget). MUFU element-rate bound.
// ---------------------------------------------------------------------------
__global__ __launch_bounds__(128) void score_kernel(const float* __restrict__ Wv)
{
    __shared__ __align__(16) uint4 qsh[HHv];
    __shared__ __align__(16) unsigned wsh[HHv];

    int t = threadIdx.x;
    int bid = blockIdx.x;
    int mc = bid & 3;
    int qc = (bid >> 2) & 63;
    int b = bid >> 8;
    int n0 = qc * 8;
    int m = mc * 128 + t;

    {
        const float* qb0 = g_q0 + (b * NQv + n0) * HHv + 2 * t;
        const float* qb1 = g_q1 + (b * NQv + n0) * HHv + 2 * t;
        float2 r[8];
#pragma unroll
        for (int q = 0; q < 8; q++) {
            float2 p0 = *(const float2*)(qb0 + q * HHv);
            float2 p1 = *(const float2*)(qb1 + q * HHv);
            r[q] = make_float2(p0.x + p1.x, p0.y + p1.y);
        }
#pragma unroll
        for (int j = 0; j < 2; j++) {
            int h = 2 * t + j;
            float v0 = j ? r[0].y : r[0].x, v1 = j ? r[1].y : r[1].x;
            float v2 = j ? r[2].y : r[2].x, v3 = j ? r[3].y : r[3].x;
            float v4 = j ? r[4].y : r[4].x, v5 = j ? r[5].y : r[5].x;
            float v6 = j ? r[6].y : r[6].x, v7 = j ? r[7].y : r[7].x;
            qsh[h] = make_uint4(packh2(v0, v1), packh2(v2, v3),
                                packh2(v4, v5), packh2(v6, v7));
        }
        float2 wv = *(const float2*)(Wv + 2 * t);
        wsh[2 * t + 0] = packh2(wv.x, wv.x);
        wsh[2 * t + 1] = packh2(wv.y, wv.y);
    }
    __syncthreads();

    float facc[8];
#pragma unroll
    for (int q = 0; q < 8; q++) facc[q] = 0.f;

    const float* kb0 = g_kT0 + (b * HHv) * MMv + m;
    const float* kb1 = g_kT1 + (b * HHv) * MMv + m;

    for (int h0 = 0; h0 < HHv; h0 += 8) {
        unsigned acc2[4] = {0u, 0u, 0u, 0u};
#pragma unroll
        for (int hh = 0; hh < 8; hh++) {
            int h = h0 + hh;
            float kv = kb0[h * MMv] + kb1[h * MMv];
            unsigned kk2 = packh2(kv, kv);
            uint4 qh = qsh[h];
            unsigned w2 = wsh[h];
            acc2[0] = hfma2(w2, htanh2(hadd2(qh.x, kk2)), acc2[0]);
            acc2[1] = hfma2(w2, htanh2(hadd2(qh.y, kk2)), acc2[1]);
            acc2[2] = hfma2(w2, htanh2(hadd2(qh.z, kk2)), acc2[2]);
            acc2[3] = hfma2(w2, htanh2(hadd2(qh.w, kk2)), acc2[3]);
        }
        drain2(acc2[0], facc[0], facc[1]);
        drain2(acc2[1], facc[2], facc[3]);
        drain2(acc2[2], facc[4], facc[5]);
        drain2(acc2[3], facc[6], facc[7]);
    }

#pragma unroll
    for (int q = 0; q < 8; q++)
        g_sc[(b * NQv + n0 + q) * MMv + m] = facc[q];
}

// ---------------------------------------------------------------------------
// Softmax + AV (R12-proven, frozen): 16q/block + v-split 2, grid 256.
// ---------------------------------------------------------------------------
__global__ __launch_bounds__(256) void softav_kernel(const float* __restrict__ value,
                                                     float* __restrict__ out)
{
    __shared__ __align__(16) float sc[16][MMv];
    __shared__ float inv_s[16];
    float2 (*ps)[16][64] = (float2(*)[16][64])sc;

    int t = threadIdx.x;
    int bid = blockIdx.x;
    int vh = bid & 1;
    int qc = (bid >> 1) & 31;
    int b = bid >> 6;
    int n0 = qc * 16;
    int w = t >> 5, lane = t & 31;

#pragma unroll
    for (int r = 0; r < 2; r++) {
        int row = 2 * w + r;
        const float* srow = g_sc + (b * NQv + n0 + row) * MMv;
        float vals[16];
        float vmax = -1e30f;
#pragma unroll
        for (int j = 0; j < 16; j++) {
            vals[j] = srow[lane + j * 32];
            vmax = fmaxf(vmax, vals[j]);
        }
#pragma unroll
        for (int o = 16; o > 0; o >>= 1)
            vmax = fmaxf(vmax, __shfl_xor_sync(0xffffffffu, vmax, o));
        float sum = 0.f;
#pragma unroll
        for (int j = 0; j < 16; j++) {
            float p = fex2((vals[j] - vmax) * 1.4426950408889634f);
            sc[row][lane + j * 32] = p;
            sum += p;
        }
#pragma unroll
        for (int o = 16; o > 0; o >>= 1)
            sum += __shfl_xor_sync(0xffffffffu, sum, o);
        if (lane == 0) inv_s[row] = 1.0f / sum;
    }
    __syncthreads();

    int mg = t >> 6;
    int vg = t & 63;
    const float* vbase = value + (b * MMv + mg * 128) * DDv + vh * 128 + vg * 2;
    unsigned long long acc[16];
#pragma unroll
    for (int q = 0; q < 16; q++) acc[q] = 0ull;

    for (int m4 = 0; m4 < 128; m4 += 4) {
        float2 v0 = *(const float2*)(vbase + (m4 + 0) * DDv);
        float2 v1 = *(const float2*)(vbase + (m4 + 1) * DDv);
        float2 v2 = *(const float2*)(vbase + (m4 + 2) * DDv);
        float2 v3 = *(const float2*)(vbase + (m4 + 3) * DDv);
        unsigned long long w0 = pk2(v0.x, v0.y);
        unsigned long long w1 = pk2(v1.x, v1.y);
        unsigned long long w2 = pk2(v2.x, v2.y);
        unsigned long long w3 = pk2(v3.x, v3.y);
        int mIdx = mg * 128 + m4;
#pragma unroll
        for (int q = 0; q < 16; q++) {
            float4 p = *(const float4*)&sc[q][mIdx];
            fma2(acc[q], pk2(p.x, p.x), w0);
            fma2(acc[q], pk2(p.y, p.y), w1);
            fma2(acc[q], pk2(p.z, p.z), w2);
            fma2(acc[q], pk2(p.w, p.w), w3);
        }
    }
    __syncthreads();
#pragma unroll
    for (int q = 0; q < 16; q++) ps[mg][q][vg] = up2(acc[q]);
    __syncthreads();

#pragma unroll
    for (int r = 0; r < 4; r++) {
        int p = t + r * 256;
        int q = p >> 6, v2i = p & 63;
        float2 s0 = ps[0][q][v2i];
        float2 s1 = ps[1][q][v2i];
        float2 s2 = ps[2][q][v2i];
        float2 s3 = ps[3][q][v2i];
        float iv = inv_s[q];
        ((float2*)out)[(b * NQv + n0 + q) * 128 + vh * 64 + v2i] =
            make_float2((s0.x + s1.x + s2.x + s3.x) * iv,
                        (s0.y + s1.y + s2.y + s3.y) * iv);
    }
}

extern "C" void kernel_launch(void* const* d_in, const int* in_sizes, int n_in,
                              void* d_out, int out_size)
{
    const float* query = (const float*)d_in[0];
    const float* key   = (const float*)d_in[1];
    const float* value = (const float*)d_in[2];
    const float* Wq    = (const float*)d_in[3];
    const float* Wk    = (const float*)d_in[4];
    const float* Wv    = (const float*)d_in[5];
    float* out = (float*)d_out;

    proj_kernel<<<512, 256>>>(query, key, Wq, Wk);
    score_kernel<<<1024, 128>>>(Wv);
    softav_kernel<<<256, 256>>>(value, out);
}